// round 8
// baseline (speedup 1.0000x reference)
#include <cuda_runtime.h>

// ---------------------------------------------------------------------------
//   x: (16,32,32,32,32) f32   w: (32,16,3,3,3)   b,gamma,beta: (16,)
//   ConvTranspose3d s=2 p=1 -> (16,16,63,63,63); BN; AvgPool4 -> (16,16,15,15,15)
//
// Parity classes (pd,ph,pw): o = 2*o2+p; p=0 -> tap k=1@i=o2; p=1 -> taps
// k=2@i=o2, k=0@i=o2+1. Pool cell o/4 = o2>>1 for both parities -> block
// owning od2 {2a,2a+1} x all classes owns pool slice a exclusively; the BN
// partial ssum IS the pool sum for interior threads.
// R5 inner structure (proven 320us) + cout split across warps for occ 6:
// block (32,8): warp = (p = oh2-pair, h = cout half); 8 cout per thread.
// ---------------------------------------------------------------------------

typedef unsigned long long ull;

static __device__ float g_sum[16];
static __device__ float g_sumsq[16];
static __device__ float g_scale[16];
static __device__ float g_shift[16];

__device__ __forceinline__ ull pack2f(float a, float b) {
    ull r; asm("mov.b64 %0, {%1, %2};" : "=l"(r) : "f"(a), "f"(b)); return r;
}
__device__ __forceinline__ void unpack2f(ull v, float& a, float& b) {
    asm("mov.b64 {%0, %1}, %2;" : "=f"(a), "=f"(b) : "l"(v));
}
__device__ __forceinline__ void ffma2(ull& d, ull a, ull b) {
    asm("fma.rn.f32x2 %0, %1, %2, %0;" : "+l"(d) : "l"(a), "l"(b));
}
__device__ __forceinline__ ull add2(ull a, ull b) {
    ull r; asm("add.rn.f32x2 %0, %1, %2;" : "=l"(r) : "l"(a), "l"(b)); return r;
}

__global__ void zero_stats_kernel() {
    int t = threadIdx.x;
    if (t < 16) { g_sum[t] = 0.f; g_sumsq[t] = 0.f; }
}

// One parity class (R5 structure). xq0 = x + n*1M + oh2b*32 + ow2.
// wsp = ws + h*8 (this warp's 8-cout slice). acc: 2 rows x 4 ull.
template <int PD, int PH, int PW>
__device__ __forceinline__ void do_class(
    const float* __restrict__ xq0, const float* __restrict__ wsp,
    const ull* __restrict__ bpak, int a, int hof2,
    bool vlane, bool v1row, ull* __restrict__ ssum, ull* __restrict__ ssq)
{
    const int NTD = 1 + PD, NTH = 1 + PH, NTW = 1 + PW;
    constexpr int UNR = (PD + PH >= 2) ? 2 : 4;

#pragma unroll 1
    for (int dd = 0; dd < 2; dd++) {
        const int od2 = 2 * a + dd;
        if (PD && od2 == 31) continue;          // od=63 invalid (uniform)
        const float* xq = xq0 + od2 * 1024;

        ull a0[4], a1[4];
#pragma unroll
        for (int q = 0; q < 4; q++) { a0[q] = bpak[q]; a1[q] = bpak[q]; }

#pragma unroll 1
        for (int ci0 = 0; ci0 < 32; ci0 += UNR) {
#pragma unroll
            for (int u = 0; u < UNR; u++) {
                const float* xp = xq + (ci0 + u) * 32768;
                float xr[2][3];
                xr[0][0] = xp[0];
                xr[0][1] = xp[32];
                if (PH) xr[0][2] = xp[hof2];
                if (PD) {
                    xr[1][0] = xp[1024];
                    xr[1][1] = xp[1056];
                    if (PH) xr[1][2] = xp[1024 + hof2];
                }
                ull xd[2][3], xs[2][3];
#pragma unroll
                for (int d = 0; d < NTD; d++)
#pragma unroll
                    for (int r = 0; r <= NTH; r++) {
                        xd[d][r] = pack2f(xr[d][r], xr[d][r]);
                        if (PW) {
                            float t = __shfl_down_sync(0xffffffffu, xr[d][r], 1);
                            xs[d][r] = pack2f(t, t);
                        }
                    }
#pragma unroll
                for (int td = 0; td < NTD; td++)
#pragma unroll
                    for (int th = 0; th < NTH; th++)
#pragma unroll
                        for (int tw = 0; tw < NTW; tw++) {
                            const int tap = (td * NTH + th) * NTW + tw;
                            const ulonglong2* wv = (const ulonglong2*)
                                (wsp + tap * 512 + (ci0 + u) * 16);
                            const ulonglong2 w01 = wv[0];
                            const ulonglong2 w23 = wv[1];
                            const ull x0 = (PW && tw) ? xs[td][th]     : xd[td][th];
                            const ull x1 = (PW && tw) ? xs[td][th + 1] : xd[td][th + 1];
                            ffma2(a0[0], x0, w01.x);
                            ffma2(a0[1], x0, w01.y);
                            ffma2(a0[2], x0, w23.x);
                            ffma2(a0[3], x0, w23.y);
                            ffma2(a1[0], x1, w01.x);
                            ffma2(a1[1], x1, w01.y);
                            ffma2(a1[2], x1, w23.x);
                            ffma2(a1[3], x1, w23.y);
                        }
            }
        }

        // mask invalid outputs (loads were clamped in-bounds)
        if (PW && !vlane) {
#pragma unroll
            for (int q = 0; q < 4; q++) { a0[q] = 0ull; a1[q] = 0ull; }
        } else if (PH && !v1row) {
#pragma unroll
            for (int q = 0; q < 4; q++) a1[q] = 0ull;
        }
#pragma unroll
        for (int q = 0; q < 4; q++) {
            ssum[q] = add2(ssum[q], add2(a0[q], a1[q]));
            ffma2(ssq[q], a0[q], a0[q]);
            ffma2(ssq[q], a1[q], a1[q]);
        }
    }
}

// Grid: x = half4 (4), y = a (16), z = n (16). Block (32,8).
// warp wid: p = wid&3 -> oh2 pair {oh2b, oh2b+1}; h = wid>>2 -> cout half.
__global__ __launch_bounds__(256, 3)
void conv_kernel(const float* __restrict__ x,
                 const float* __restrict__ w,
                 const float* __restrict__ bias,
                 float* __restrict__ out)
{
    const int half4 = blockIdx.x;
    const int a     = blockIdx.y;
    const int n     = blockIdx.z;
    const int tx  = threadIdx.x;
    const int wid = threadIdx.y;
    const int tid = wid * 32 + tx;
    const int p = wid & 3;
    const int h = wid >> 2;
    const int ow2  = tx;
    const int oh2b = half4 * 8 + 2 * p;       // even, 0..30

    __shared__ __align__(16) float ws[8 * 512];
    __shared__ float sred[32];
    __shared__ float bsh[16];

    if (tid < 32) sred[tid] = 0.f;
    if (tid < 16) bsh[tid] = bias[tid];

    ull ssum[4], ssq[4];
#pragma unroll
    for (int q = 0; q < 4; q++) { ssum[q] = 0ull; ssq[q] = 0ull; }

    const int hof2 = (oh2b == 30) ? 32 : 64;  // clamped row oh2b+2 offset
    const float* xq0 = x + (size_t)n * 1048576 + oh2b * 32 + ow2;
    const bool poolok = (a < 15) && (oh2b < 30) && (ow2 < 30);

    for (int cls = 0; cls < 8; cls++) {
        const int pd = (cls >> 2) & 1, ph = (cls >> 1) & 1, pw = cls & 1;
        const int ntd = 1 + pd, nth = 1 + ph, ntw = 1 + pw;
        const int ntap = ntd * nth * ntw;

        __syncthreads();
        for (int i = tid; i < ntap * 512; i += 256) {
            int t = i >> 9, e = i & 511;
            int tw = t % ntw, th = (t / ntw) % nth, td = t / (ntw * nth);
            int kd = pd ? 2 - 2 * td : 1;
            int kh = ph ? 2 - 2 * th : 1;
            int kw = pw ? 2 - 2 * tw : 1;
            int ci = e >> 4, co = e & 15;
            ws[i] = w[(ci * 16 + co) * 27 + kd * 9 + kh * 3 + kw];
        }
        __syncthreads();

        ull bpak[4];
#pragma unroll
        for (int q = 0; q < 4; q++)
            bpak[q] = pack2f(bsh[h * 8 + 2 * q], bsh[h * 8 + 2 * q + 1]);

        const bool vlane = (!pw) || (ow2 < 31);
        const bool v1row = (!ph) || (oh2b < 30);
        const float* wsp = ws + h * 8;

        switch (cls) {
            case 0: do_class<0,0,0>(xq0, wsp, bpak, a, hof2, vlane, v1row, ssum, ssq); break;
            case 1: do_class<0,0,1>(xq0, wsp, bpak, a, hof2, vlane, v1row, ssum, ssq); break;
            case 2: do_class<0,1,0>(xq0, wsp, bpak, a, hof2, vlane, v1row, ssum, ssq); break;
            case 3: do_class<0,1,1>(xq0, wsp, bpak, a, hof2, vlane, v1row, ssum, ssq); break;
            case 4: do_class<1,0,0>(xq0, wsp, bpak, a, hof2, vlane, v1row, ssum, ssq); break;
            case 5: do_class<1,0,1>(xq0, wsp, bpak, a, hof2, vlane, v1row, ssum, ssq); break;
            case 6: do_class<1,1,0>(xq0, wsp, bpak, a, hof2, vlane, v1row, ssum, ssq); break;
            case 7: do_class<1,1,1>(xq0, wsp, bpak, a, hof2, vlane, v1row, ssum, ssq); break;
        }
    }

    // ---- pool write straight from ssum (== pool sum for poolok threads) ----
    {
        const int ph4 = half4 * 4 + p;
        const int pw4 = ow2 >> 1;
        const size_t base =
            ((((size_t)n * 16) * 15 + a) * 15 + ph4) * 15 + pw4;
#pragma unroll
        for (int j = 0; j < 4; j++) {
            float sl, sh;
            unpack2f(ssum[j], sl, sh);
            float sl2 = __shfl_down_sync(0xffffffffu, sl, 1);
            float sh2 = __shfl_down_sync(0xffffffffu, sh, 1);
            if (poolok && !(ow2 & 1)) {
                out[base + (size_t)(h * 8 + 2 * j)     * 3375] = sl + sl2;
                out[base + (size_t)(h * 8 + 2 * j + 1) * 3375] = sh + sh2;
            }
        }
    }

    // ---- stats reduce: warp shuffle -> smem -> global atomics ----
#pragma unroll
    for (int j = 0; j < 4; j++) {
        float sl, sh, ql, qh;
        unpack2f(ssum[j], sl, sh);
        unpack2f(ssq[j],  ql, qh);
#pragma unroll
        for (int o = 16; o >= 1; o >>= 1) {
            sl += __shfl_xor_sync(0xffffffffu, sl, o);
            sh += __shfl_xor_sync(0xffffffffu, sh, o);
            ql += __shfl_xor_sync(0xffffffffu, ql, o);
            qh += __shfl_xor_sync(0xffffffffu, qh, o);
        }
        if (tx == 0) {
            atomicAdd(&sred[h * 8 + 2 * j],          sl);
            atomicAdd(&sred[h * 8 + 2 * j + 1],      sh);
            atomicAdd(&sred[16 + h * 8 + 2 * j],     ql);
            atomicAdd(&sred[16 + h * 8 + 2 * j + 1], qh);
        }
    }
    __syncthreads();
    if (tid < 16)      atomicAdd(&g_sum[tid],        sred[tid]);
    else if (tid < 32) atomicAdd(&g_sumsq[tid - 16], sred[tid]);
}

__global__ void stats_kernel(const float* __restrict__ gamma,
                             const float* __restrict__ beta) {
    int c = threadIdx.x;
    if (c >= 16) return;
    const float inv_cnt = 1.0f / 4000752.0f;   // 16 * 63^3
    float mean = g_sum[c] * inv_cnt;
    float var  = g_sumsq[c] * inv_cnt - mean * mean;
    float inv  = rsqrtf(var + 1e-5f);
    float sc   = gamma[c] * inv;
    g_scale[c] = sc;
    g_shift[c] = beta[c] - mean * sc;
}

__global__ __launch_bounds__(256)
void affine_kernel(float* __restrict__ out) {
    int idx = blockIdx.x * 256 + threadIdx.x;
    if (idx >= 864000) return;
    int co = (idx / 3375) & 15;
    out[idx] = out[idx] * (1.0f / 64.0f) * g_scale[co] + g_shift[co];
}

extern "C" void kernel_launch(void* const* d_in, const int* in_sizes, int n_in,
                              void* d_out, int out_size) {
    const float* x     = (const float*)d_in[0];
    const float* w     = (const float*)d_in[1];
    const float* b     = (const float*)d_in[2];
    const float* gamma = (const float*)d_in[3];
    const float* beta  = (const float*)d_in[4];
    float* out = (float*)d_out;

    zero_stats_kernel<<<1, 32>>>();
    dim3 grid(4, 16, 16), blk(32, 8);
    conv_kernel<<<grid, blk>>>(x, w, b, out);
    stats_kernel<<<1, 16>>>(gamma, beta);
    affine_kernel<<<3375, 256>>>(out);
}

// round 9
// speedup vs baseline: 1.0965x; 1.0965x over previous
#include <cuda_runtime.h>

// ---------------------------------------------------------------------------
//   x: (16,32,32,32,32) f32   w: (32,16,3,3,3)   b,gamma,beta: (16,)
//   ConvTranspose3d s=2 p=1 -> (16,16,63,63,63); BN; AvgPool4 -> (16,16,15,15,15)
//
// Parity classes (pd,ph,pw): o = 2*o2+p; p=0 -> tap k=1@i=o2; p=1 -> taps
// k=2@i=o2, k=0@i=o2+1. Pool cell o/4 = o2>>1 for both parities -> block
// owning od2 {2a,2a+1} x all classes owns pool slice a exclusively; the BN
// partial ssum IS the pool sum for interior threads.
// R5 structure (proven 320us): block (32,4), lane=ow2, warp=oh2-pair,
// 16 cout packed f32x2 per thread. Deltas: bias packed in smem (frees 16
// regs), UNR=4 in ALL classes (MLP x2 in the 44%-of-work heavy classes),
// stats zeroing folded into stats_kernel (read-reset).
// ---------------------------------------------------------------------------

typedef unsigned long long ull;

static __device__ float g_sum[16];
static __device__ float g_sumsq[16];
static __device__ float g_scale[16];
static __device__ float g_shift[16];

__device__ __forceinline__ ull pack2f(float a, float b) {
    ull r; asm("mov.b64 %0, {%1, %2};" : "=l"(r) : "f"(a), "f"(b)); return r;
}
__device__ __forceinline__ void unpack2f(ull v, float& a, float& b) {
    asm("mov.b64 {%0, %1}, %2;" : "=f"(a), "=f"(b) : "l"(v));
}
__device__ __forceinline__ void ffma2(ull& d, ull a, ull b) {
    asm("fma.rn.f32x2 %0, %1, %2, %0;" : "+l"(d) : "l"(a), "l"(b));
}
__device__ __forceinline__ ull add2(ull a, ull b) {
    ull r; asm("add.rn.f32x2 %0, %1, %2;" : "=l"(r) : "l"(a), "l"(b)); return r;
}

// One parity class. xq0 = x + n*1M + oh2b*32 + ow2. bpsh = packed bias (smem).
template <int PD, int PH, int PW>
__device__ __forceinline__ void do_class(
    const float* __restrict__ xq0, const float* __restrict__ ws,
    const ull* __restrict__ bpsh, int a, int hof2,
    bool vlane, bool v1row, ull* __restrict__ ssum, ull* __restrict__ ssq)
{
    const int NTD = 1 + PD, NTH = 1 + PH, NTW = 1 + PW;
    constexpr int UNR = 4;

#pragma unroll 1
    for (int dd = 0; dd < 2; dd++) {
        const int od2 = 2 * a + dd;
        if (PD && od2 == 31) continue;          // od=63 invalid (uniform)
        const float* xq = xq0 + od2 * 1024;

        ull a0[8], a1[8];
#pragma unroll
        for (int j = 0; j < 8; j++) { a0[j] = bpsh[j]; a1[j] = bpsh[j]; }

#pragma unroll 1
        for (int ci0 = 0; ci0 < 32; ci0 += UNR) {
#pragma unroll
            for (int u = 0; u < UNR; u++) {
                const float* xp = xq + (ci0 + u) * 32768;
                float xr[2][3];
                xr[0][0] = xp[0];
                xr[0][1] = xp[32];
                if (PH) xr[0][2] = xp[hof2];
                if (PD) {
                    xr[1][0] = xp[1024];
                    xr[1][1] = xp[1056];
                    if (PH) xr[1][2] = xp[1024 + hof2];
                }
                ull xd[2][3], xs[2][3];
#pragma unroll
                for (int d = 0; d < NTD; d++)
#pragma unroll
                    for (int r = 0; r <= NTH; r++) {
                        xd[d][r] = pack2f(xr[d][r], xr[d][r]);
                        if (PW) {
                            float t = __shfl_down_sync(0xffffffffu, xr[d][r], 1);
                            xs[d][r] = pack2f(t, t);
                        }
                    }
#pragma unroll
                for (int td = 0; td < NTD; td++)
#pragma unroll
                    for (int th = 0; th < NTH; th++)
#pragma unroll
                        for (int tw = 0; tw < NTW; tw++) {
                            const int tap = (td * NTH + th) * NTW + tw;
                            const ulonglong2* wv = (const ulonglong2*)
                                (ws + tap * 512 + (ci0 + u) * 16);
                            const ull x0 = (PW && tw) ? xs[td][th]     : xd[td][th];
                            const ull x1 = (PW && tw) ? xs[td][th + 1] : xd[td][th + 1];
#pragma unroll
                            for (int q = 0; q < 4; q++) {
                                ulonglong2 wq = wv[q];
                                ffma2(a0[2 * q],     x0, wq.x);
                                ffma2(a0[2 * q + 1], x0, wq.y);
                                ffma2(a1[2 * q],     x1, wq.x);
                                ffma2(a1[2 * q + 1], x1, wq.y);
                            }
                        }
            }
        }

        // mask invalid outputs (loads were clamped in-bounds)
        if (PW && !vlane) {
#pragma unroll
            for (int j = 0; j < 8; j++) { a0[j] = 0ull; a1[j] = 0ull; }
        } else if (PH && !v1row) {
#pragma unroll
            for (int j = 0; j < 8; j++) a1[j] = 0ull;
        }
#pragma unroll
        for (int j = 0; j < 8; j++) {
            ssum[j] = add2(ssum[j], add2(a0[j], a1[j]));
            ffma2(ssq[j], a0[j], a0[j]);
            ffma2(ssq[j], a1[j], a1[j]);
        }
    }
}

// Grid: x = half4 (4), y = a (16), z = n (16). Block (32,4).
// lane = ow2; warp ty -> output rows {oh2b, oh2b+1}; 16 cout packed.
__global__ __launch_bounds__(128, 4)
void conv_kernel(const float* __restrict__ x,
                 const float* __restrict__ w,
                 const float* __restrict__ bias,
                 float* __restrict__ out)
{
    const int half4 = blockIdx.x;
    const int a     = blockIdx.y;
    const int n     = blockIdx.z;
    const int tx = threadIdx.x, ty = threadIdx.y;
    const int tid = ty * 32 + tx;
    const int ow2 = tx;
    const int oh2b = half4 * 8 + 2 * ty;      // even, 0..30

    __shared__ __align__(16) float ws[8 * 512];
    __shared__ ull bpsh[8];
    __shared__ float sred[32];

    if (tid < 32) sred[tid] = 0.f;
    if (tid < 8)  bpsh[tid] = pack2f(bias[2 * tid], bias[2 * tid + 1]);

    ull ssum[8], ssq[8];
#pragma unroll
    for (int j = 0; j < 8; j++) { ssum[j] = 0ull; ssq[j] = 0ull; }

    const int hof2 = (oh2b == 30) ? 32 : 64;  // clamped row oh2b+2 offset
    const float* xq0 = x + (size_t)n * 1048576 + oh2b * 32 + ow2;
    const bool poolok = (a < 15) && (oh2b < 30) && (ow2 < 30);

    for (int cls = 0; cls < 8; cls++) {
        const int pd = (cls >> 2) & 1, ph = (cls >> 1) & 1, pw = cls & 1;
        const int ntd = 1 + pd, nth = 1 + ph, ntw = 1 + pw;
        const int ntap = ntd * nth * ntw;

        __syncthreads();
        for (int i = tid; i < ntap * 512; i += 128) {
            int t = i >> 9, e = i & 511;
            int tw = t % ntw, th = (t / ntw) % nth, td = t / (ntw * nth);
            int kd = pd ? 2 - 2 * td : 1;
            int kh = ph ? 2 - 2 * th : 1;
            int kw = pw ? 2 - 2 * tw : 1;
            int ci = e >> 4, co = e & 15;
            ws[i] = w[(ci * 16 + co) * 27 + kd * 9 + kh * 3 + kw];
        }
        __syncthreads();

        const bool vlane = (!pw) || (ow2 < 31);
        const bool v1row = (!ph) || (oh2b < 30);

        switch (cls) {
            case 0: do_class<0,0,0>(xq0, ws, bpsh, a, hof2, vlane, v1row, ssum, ssq); break;
            case 1: do_class<0,0,1>(xq0, ws, bpsh, a, hof2, vlane, v1row, ssum, ssq); break;
            case 2: do_class<0,1,0>(xq0, ws, bpsh, a, hof2, vlane, v1row, ssum, ssq); break;
            case 3: do_class<0,1,1>(xq0, ws, bpsh, a, hof2, vlane, v1row, ssum, ssq); break;
            case 4: do_class<1,0,0>(xq0, ws, bpsh, a, hof2, vlane, v1row, ssum, ssq); break;
            case 5: do_class<1,0,1>(xq0, ws, bpsh, a, hof2, vlane, v1row, ssum, ssq); break;
            case 6: do_class<1,1,0>(xq0, ws, bpsh, a, hof2, vlane, v1row, ssum, ssq); break;
            case 7: do_class<1,1,1>(xq0, ws, bpsh, a, hof2, vlane, v1row, ssum, ssq); break;
        }
    }

    // ---- pool write straight from ssum (== pool sum for poolok threads) ----
    {
        const int ph4 = half4 * 4 + ty;
        const int pw4 = ow2 >> 1;
        const size_t base =
            ((((size_t)n * 16) * 15 + a) * 15 + ph4) * 15 + pw4;
#pragma unroll
        for (int j = 0; j < 8; j++) {
            float sl, sh;
            unpack2f(ssum[j], sl, sh);
            float sl2 = __shfl_down_sync(0xffffffffu, sl, 1);
            float sh2 = __shfl_down_sync(0xffffffffu, sh, 1);
            if (poolok && !(ow2 & 1)) {
                out[base + (size_t)(2 * j)     * 3375] = sl + sl2;
                out[base + (size_t)(2 * j + 1) * 3375] = sh + sh2;
            }
        }
    }

    // ---- stats reduce: warp shuffle -> smem -> 32 global atomics ----
#pragma unroll
    for (int j = 0; j < 8; j++) {
        float sl, sh, ql, qh;
        unpack2f(ssum[j], sl, sh);
        unpack2f(ssq[j],  ql, qh);
#pragma unroll
        for (int o = 16; o >= 1; o >>= 1) {
            sl += __shfl_xor_sync(0xffffffffu, sl, o);
            sh += __shfl_xor_sync(0xffffffffu, sh, o);
            ql += __shfl_xor_sync(0xffffffffu, ql, o);
            qh += __shfl_xor_sync(0xffffffffu, qh, o);
        }
        if (tx == 0) {
            atomicAdd(&sred[2 * j],          sl);
            atomicAdd(&sred[2 * j + 1],      sh);
            atomicAdd(&sred[16 + 2 * j],     ql);
            atomicAdd(&sred[16 + 2 * j + 1], qh);
        }
    }
    __syncthreads();
    if (tid < 16)      atomicAdd(&g_sum[tid],        sred[tid]);
    else if (tid < 32) atomicAdd(&g_sumsq[tid - 16], sred[tid]);
}

// Reads accumulated stats, computes BN affine coeffs, resets accumulators
// (so every graph replay starts from zero — deterministic).
__global__ void stats_kernel(const float* __restrict__ gamma,
                             const float* __restrict__ beta) {
    int c = threadIdx.x;
    if (c >= 16) return;
    float s = g_sum[c], q = g_sumsq[c];
    g_sum[c] = 0.f; g_sumsq[c] = 0.f;
    const float inv_cnt = 1.0f / 4000752.0f;   // 16 * 63^3
    float mean = s * inv_cnt;
    float var  = q * inv_cnt - mean * mean;
    float inv  = rsqrtf(var + 1e-5f);
    float sc   = gamma[c] * inv;
    g_scale[c] = sc;
    g_shift[c] = beta[c] - mean * sc;
}

__global__ __launch_bounds__(256)
void affine_kernel(float* __restrict__ out) {
    int idx = blockIdx.x * 256 + threadIdx.x;
    if (idx >= 864000) return;
    int co = (idx / 3375) & 15;
    out[idx] = out[idx] * (1.0f / 64.0f) * g_scale[co] + g_shift[co];
}

extern "C" void kernel_launch(void* const* d_in, const int* in_sizes, int n_in,
                              void* d_out, int out_size) {
    const float* x     = (const float*)d_in[0];
    const float* w     = (const float*)d_in[1];
    const float* b     = (const float*)d_in[2];
    const float* gamma = (const float*)d_in[3];
    const float* beta  = (const float*)d_in[4];
    float* out = (float*)d_out;

    dim3 grid(4, 16, 16), blk(32, 4);
    conv_kernel<<<grid, blk>>>(x, w, b, out);
    stats_kernel<<<1, 16>>>(gamma, beta);
    affine_kernel<<<3375, 256>>>(out);
}

// round 17
// speedup vs baseline: 1.1401x; 1.0398x over previous
#include <cuda_runtime.h>

// ---------------------------------------------------------------------------
//   x: (16,32,32,32,32) f32   w: (32,16,3,3,3)   b,gamma,beta: (16,)
//   ConvTranspose3d s=2 p=1 -> (16,16,63,63,63); BN; AvgPool4 -> (16,16,15,15,15)
//
// Parity classes (pd,ph,pw). Block owns pool-d slice a (od2 {2a,2a+1}) x all
// 8 classes -> exclusive pool cells; BN partial ssum IS the pool sum for
// interior threads. Thread = (lane=ow2, warp -> (oh2-pair p, cout-half h)):
// 4 output rows (2 od2 x 2 oh) x 8 cout packed f32x2 -> one 2xLDS.128
// weight fetch feeds 16 FFMA2 (halves l1tex traffic vs 2-row layout).
// ---------------------------------------------------------------------------

typedef unsigned long long ull;

static __device__ float g_sum[16];
static __device__ float g_sumsq[16];
static __device__ float g_scale[16];
static __device__ float g_shift[16];

__device__ __forceinline__ ull pack2f(float a, float b) {
    ull r; asm("mov.b64 %0, {%1, %2};" : "=l"(r) : "f"(a), "f"(b)); return r;
}
__device__ __forceinline__ void unpack2f(ull v, float& a, float& b) {
    asm("mov.b64 {%0, %1}, %2;" : "=f"(a), "=f"(b) : "l"(v));
}
__device__ __forceinline__ void ffma2(ull& d, ull a, ull b) {
    asm("fma.rn.f32x2 %0, %1, %2, %0;" : "+l"(d) : "l"(a), "l"(b));
}
__device__ __forceinline__ ull add2(ull a, ull b) {
    ull r; asm("add.rn.f32x2 %0, %1, %2;" : "=l"(r) : "l"(a), "l"(b)); return r;
}

// One parity class. xb = x + n*1M + 2a*1024 + oh2b*32 + ow2.
// wsp = ws + h*8 (this warp's cout half). acc rows: [dd*2 + r].
template <int PD, int PH, int PW>
__device__ __forceinline__ void do_class(
    const float* __restrict__ xb, const float* __restrict__ wsp,
    const ull* __restrict__ bpak, int d2off, int hof2,
    bool lane31, bool hedge, bool dedge,
    ull* __restrict__ ssum, ull* __restrict__ ssq)
{
    const int ND = 2 + PD, NR = 2 + PH;
    const int NTD = 1 + PD, NTH = 1 + PH, NTW = 1 + PW;
    const int doff[3] = {0, 1024, d2off};
    const int roff[3] = {0, 32, hof2};
    constexpr int UNR = (PD + PH >= 2) ? 2 : 4;

    ull acc[4][4];
#pragma unroll
    for (int k = 0; k < 4; k++)
#pragma unroll
        for (int q = 0; q < 4; q++) acc[k][q] = bpak[q];

#pragma unroll 1
    for (int ci0 = 0; ci0 < 32; ci0 += UNR) {
        float xr[UNR][3][3];
#pragma unroll
        for (int u = 0; u < UNR; u++)
#pragma unroll
            for (int d = 0; d < ND; d++)
#pragma unroll
                for (int r = 0; r < NR; r++)
                    xr[u][d][r] = xb[(ci0 + u) * 32768 + doff[d] + roff[r]];

#pragma unroll
        for (int u = 0; u < UNR; u++) {
            ull xd[3][3];
#pragma unroll
            for (int d = 0; d < ND; d++)
#pragma unroll
                for (int r = 0; r < NR; r++)
                    xd[d][r] = pack2f(xr[u][d][r], xr[u][d][r]);

#pragma unroll
            for (int tw = 0; tw < NTW; tw++) {
                if (PW && tw == 1) {
#pragma unroll
                    for (int d = 0; d < ND; d++)
#pragma unroll
                        for (int r = 0; r < NR; r++)
                            xd[d][r] = __shfl_down_sync(0xffffffffu, xd[d][r], 1);
                }
#pragma unroll
                for (int td = 0; td < NTD; td++)
#pragma unroll
                    for (int th = 0; th < NTH; th++) {
                        const int tap = (td * NTH + th) * NTW + tw;
                        const ulonglong2* wv = (const ulonglong2*)
                            (wsp + tap * 512 + (ci0 + u) * 16);
                        const ulonglong2 w01 = wv[0];
                        const ulonglong2 w23 = wv[1];
#pragma unroll
                        for (int dd = 0; dd < 2; dd++)
#pragma unroll
                            for (int r = 0; r < 2; r++) {
                                const ull xo = xd[dd + PD * td][r + PH * th];
                                ull* ar = acc[dd * 2 + r];
                                ffma2(ar[0], xo, w01.x);
                                ffma2(ar[1], xo, w01.y);
                                ffma2(ar[2], xo, w23.x);
                                ffma2(ar[3], xo, w23.y);
                            }
                    }
            }
        }
    }

    // post-hoc masking of invalid outputs (loads were clamped in-bounds)
    if (PW && lane31) {
#pragma unroll
        for (int k = 0; k < 4; k++)
#pragma unroll
            for (int q = 0; q < 4; q++) acc[k][q] = 0ull;
    } else {
        if (PH && hedge) {
#pragma unroll
            for (int q = 0; q < 4; q++) { acc[1][q] = 0ull; acc[3][q] = 0ull; }
        }
        if (PD && dedge) {
#pragma unroll
            for (int q = 0; q < 4; q++) { acc[2][q] = 0ull; acc[3][q] = 0ull; }
        }
    }

#pragma unroll
    for (int q = 0; q < 4; q++)
#pragma unroll
        for (int k = 0; k < 4; k++) {
            ssum[q] = add2(ssum[q], acc[k][q]);
            ffma2(ssq[q], acc[k][q], acc[k][q]);
        }
}

// Grid: x = half4 (4), y = a (16), z = n (16). Block (32,8).
// warp wid: p = wid&3 -> oh2 pair {oh2b, oh2b+1}; h = wid>>2 -> cout half.
__global__ __launch_bounds__(256, 3)
void conv_kernel(const float* __restrict__ x,
                 const float* __restrict__ w,
                 const float* __restrict__ bias,
                 float* __restrict__ out)
{
    const int half4 = blockIdx.x;
    const int a     = blockIdx.y;
    const int n     = blockIdx.z;
    const int tx  = threadIdx.x;
    const int wid = threadIdx.y;
    const int tid = wid * 32 + tx;
    const int p = wid & 3;
    const int h = wid >> 2;
    const int ow2  = tx;
    const int oh2b = half4 * 8 + 2 * p;       // even, 0..30

    __shared__ __align__(16) float ws[8 * 512];
    __shared__ float sred[32];
    __shared__ float bsh[16];

    if (tid < 32) sred[tid] = 0.f;
    if (tid < 16) bsh[tid] = bias[tid];

    ull ssum[4], ssq[4];
#pragma unroll
    for (int q = 0; q < 4; q++) { ssum[q] = 0ull; ssq[q] = 0ull; }

    const int hof2  = (oh2b == 30) ? 32 : 64;   // clamped row oh2b+2
    const int d2off = (a == 15) ? 1024 : 2048;  // clamped depth 2a+2
    const bool lane31 = (ow2 == 31);
    const bool hedge  = (oh2b == 30);
    const bool dedge  = (a == 15);
    const float* xb = x + (size_t)n * 1048576 + (size_t)a * 2048
                        + oh2b * 32 + ow2;
    const float* wsp = ws + h * 8;
    const bool poolok = (a < 15) && (oh2b < 30) && (ow2 < 30);

    for (int cls = 0; cls < 8; cls++) {
        const int pd = (cls >> 2) & 1, ph = (cls >> 1) & 1, pw = cls & 1;
        const int ntd = 1 + pd, nth = 1 + ph, ntw = 1 + pw;
        const int ntap = ntd * nth * ntw;

        __syncthreads();
        for (int i = tid; i < ntap * 512; i += 256) {
            int t = i >> 9, e = i & 511;
            int tw = t % ntw, th = (t / ntw) % nth, td = t / (ntw * nth);
            int kd = pd ? 2 - 2 * td : 1;
            int kh = ph ? 2 - 2 * th : 1;
            int kw = pw ? 2 - 2 * tw : 1;
            int ci = e >> 4, co = e & 15;
            ws[i] = w[(ci * 16 + co) * 27 + kd * 9 + kh * 3 + kw];
        }
        __syncthreads();

        ull bpak[4];
#pragma unroll
        for (int q = 0; q < 4; q++)
            bpak[q] = pack2f(bsh[h * 8 + 2 * q], bsh[h * 8 + 2 * q + 1]);

        switch (cls) {
            case 0: do_class<0,0,0>(xb, wsp, bpak, d2off, hof2, lane31, hedge, dedge, ssum, ssq); break;
            case 1: do_class<0,0,1>(xb, wsp, bpak, d2off, hof2, lane31, hedge, dedge, ssum, ssq); break;
            case 2: do_class<0,1,0>(xb, wsp, bpak, d2off, hof2, lane31, hedge, dedge, ssum, ssq); break;
            case 3: do_class<0,1,1>(xb, wsp, bpak, d2off, hof2, lane31, hedge, dedge, ssum, ssq); break;
            case 4: do_class<1,0,0>(xb, wsp, bpak, d2off, hof2, lane31, hedge, dedge, ssum, ssq); break;
            case 5: do_class<1,0,1>(xb, wsp, bpak, d2off, hof2, lane31, hedge, dedge, ssum, ssq); break;
            case 6: do_class<1,1,0>(xb, wsp, bpak, d2off, hof2, lane31, hedge, dedge, ssum, ssq); break;
            case 7: do_class<1,1,1>(xb, wsp, bpak, d2off, hof2, lane31, hedge, dedge, ssum, ssq); break;
        }
    }

    // ---- pool write straight from ssum (== pool sum for poolok threads) ----
    {
        const int ph4 = half4 * 4 + p;
        const int pw4 = ow2 >> 1;
        const size_t base =
            ((((size_t)n * 16) * 15 + a) * 15 + ph4) * 15 + pw4;
#pragma unroll
        for (int j = 0; j < 4; j++) {
            float sl, sh;
            unpack2f(ssum[j], sl, sh);
            float sl2 = __shfl_down_sync(0xffffffffu, sl, 1);
            float sh2 = __shfl_down_sync(0xffffffffu, sh, 1);
            if (poolok && !(ow2 & 1)) {
                out[base + (size_t)(h * 8 + 2 * j)     * 3375] = sl + sl2;
                out[base + (size_t)(h * 8 + 2 * j + 1) * 3375] = sh + sh2;
            }
        }
    }

    // ---- stats reduce: warp shuffle -> smem -> global atomics ----
#pragma unroll
    for (int j = 0; j < 4; j++) {
        float sl, sh, ql, qh;
        unpack2f(ssum[j], sl, sh);
        unpack2f(ssq[j],  ql, qh);
#pragma unroll
        for (int o = 16; o >= 1; o >>= 1) {
            sl += __shfl_xor_sync(0xffffffffu, sl, o);
            sh += __shfl_xor_sync(0xffffffffu, sh, o);
            ql += __shfl_xor_sync(0xffffffffu, ql, o);
            qh += __shfl_xor_sync(0xffffffffu, qh, o);
        }
        if (tx == 0) {
            atomicAdd(&sred[h * 8 + 2 * j],          sl);
            atomicAdd(&sred[h * 8 + 2 * j + 1],      sh);
            atomicAdd(&sred[16 + h * 8 + 2 * j],     ql);
            atomicAdd(&sred[16 + h * 8 + 2 * j + 1], qh);
        }
    }
    __syncthreads();
    if (tid < 16)      atomicAdd(&g_sum[tid],        sred[tid]);
    else if (tid < 32) atomicAdd(&g_sumsq[tid - 16], sred[tid]);
}

// Reads accumulated stats, computes BN affine coeffs, resets accumulators
// (every graph replay starts from zero — deterministic).
__global__ void stats_kernel(const float* __restrict__ gamma,
                             const float* __restrict__ beta) {
    int c = threadIdx.x;
    if (c >= 16) return;
    float s = g_sum[c], q = g_sumsq[c];
    g_sum[c] = 0.f; g_sumsq[c] = 0.f;
    const float inv_cnt = 1.0f / 4000752.0f;   // 16 * 63^3
    float mean = s * inv_cnt;
    float var  = q * inv_cnt - mean * mean;
    float inv  = rsqrtf(var + 1e-5f);
    float sc   = gamma[c] * inv;
    g_scale[c] = sc;
    g_shift[c] = beta[c] - mean * sc;
}

__global__ __launch_bounds__(256)
void affine_kernel(float* __restrict__ out) {
    int idx = blockIdx.x * 256 + threadIdx.x;
    if (idx >= 864000) return;
    int co = (idx / 3375) & 15;
    out[idx] = out[idx] * (1.0f / 64.0f) * g_scale[co] + g_shift[co];
}

extern "C" void kernel_launch(void* const* d_in, const int* in_sizes, int n_in,
                              void* d_out, int out_size) {
    const float* x     = (const float*)d_in[0];
    const float* w     = (const float*)d_in[1];
    const float* b     = (const float*)d_in[2];
    const float* gamma = (const float*)d_in[3];
    const float* beta  = (const float*)d_in[4];
    float* out = (float*)d_out;

    dim3 grid(4, 16, 16), blk(32, 8);
    conv_kernel<<<grid, blk>>>(x, w, b, out);
    stats_kernel<<<1, 16>>>(gamma, beta);
    affine_kernel<<<3375, 256>>>(out);
}